// round 14
// baseline (speedup 1.0000x reference)
#include <cuda_runtime.h>
#include <cuda_fp16.h>

#define Bb 2
#define Qq 2048
#define Kq 2048
#define DMm 512
#define Hh 8
#define Ff 5
#define DHh 64
#define LOG2E 1.4426950408889634f
#define M0OFF 12.0f   // fixed softmax offset (folded into bias table)

// bias table: d^2-indexed, LERP, float2 pairs (t0, delta); lives in GLOBAL (L1-cached)
#define TABF 1024
#define TABC 4096
#define TABT (TABF + TABC)
#define U_COARSE_MAX 202.0f

// ---------------- scratch (__device__ globals; no allocation allowed) ----------------
__device__ __half g_sx[3][Bb*Qq*DMm];    // qs/ks/vs converted to fp16
__device__ __half g_wt[4][DMm*DMm];      // W transposed [n][k], fp16
__device__ __half g_qh[Bb*Qq*DMm];       // projected Q fp16
__device__ __half g_kh[Bb*Kq*DMm];       // projected K fp16
__device__ __half g_vt[Bb*Hh*DHh*Kq];    // projected V fp16, transposed [b][h][d][key]
__device__ __half g_ct[Bb*Qq*DMm];       // ctx fp16
__device__ float2 g_tab2[Hh*TABT];       // (bias*LOG2E - M0)[i], delta pairs

// ---------------- helpers ----------------
__device__ __forceinline__ unsigned pack_h2(float a, float b){
    __half2 h = __floats2half2_rn(a, b);
    return *reinterpret_cast<unsigned*>(&h);
}
__device__ __forceinline__ void mma_f16(float c[4], const unsigned a[4], const unsigned b[2]){
    asm volatile(
        "mma.sync.aligned.m16n8k16.row.col.f32.f16.f16.f32 "
        "{%0,%1,%2,%3},{%4,%5,%6,%7},{%8,%9},{%0,%1,%2,%3};\n"
        : "+f"(c[0]), "+f"(c[1]), "+f"(c[2]), "+f"(c[3])
        : "r"(a[0]), "r"(a[1]), "r"(a[2]), "r"(a[3]), "r"(b[0]), "r"(b[1]));
}
__device__ __forceinline__ void ldsm4(unsigned r[4], const __half* p){
    unsigned a = (unsigned)__cvta_generic_to_shared(p);
    asm volatile("ldmatrix.sync.aligned.m8n8.x4.shared.b16 {%0,%1,%2,%3}, [%4];\n"
        : "=r"(r[0]), "=r"(r[1]), "=r"(r[2]), "=r"(r[3]) : "r"(a));
}
__device__ __forceinline__ float ex2f(float x){
    float y; asm("ex2.approx.f32 %0, %1;" : "=f"(y) : "f"(x)); return y;
}
__device__ __forceinline__ void cp16(void* sdst, const void* gsrc){
    unsigned s = (unsigned)__cvta_generic_to_shared(sdst);
    asm volatile("cp.async.cg.shared.global [%0], [%1], 16;\n" :: "r"(s), "l"(gsrc));
}
#define CP_COMMIT() asm volatile("cp.async.commit_group;\n" ::: "memory")
#define CP_WAIT0()  asm volatile("cp.async.wait_group 0;\n" ::: "memory")
#define CP_WAIT1()  asm volatile("cp.async.wait_group 1;\n" ::: "memory")
#define GRP_BAR(g)  asm volatile("bar.sync %0, 256;\n" :: "r"((g)+1) : "memory")

// ---------------- bias table ----------------
__device__ __forceinline__ float tisa_bias(int h, float d,
                                           const float* a, const float* b, const float* c){
    float s = 0.f;
    #pragma unroll
    for (int f = 0; f < Ff; f++){
        float af = a[h*Ff + f];
        float bf = fabsf(b[h*Ff + f]);
        float cf = c[h*Ff + f];
        float t  = d - cf;
        s += af * expf(-bf * t * t);
    }
    return s * LOG2E - M0OFF;
}

__global__ void build_tab_kernel(const float* __restrict__ a,
                                 const float* __restrict__ b,
                                 const float* __restrict__ c){
    int h = blockIdx.x;
    for (int i = threadIdx.x; i < TABT; i += blockDim.x){
        float u0, u1;
        if (i < TABF){
            u0 = (float)i     * (1.0f/(TABF-1));
            u1 = (float)(i+1) * (1.0f/(TABF-1));
        } else {
            u0 = (float)(i - TABF)     * (U_COARSE_MAX/(TABC-1));
            u1 = (float)(i - TABF + 1) * (U_COARSE_MAX/(TABC-1));
        }
        float t0 = tisa_bias(h, sqrtf(u0), a, b, c);
        float t1 = tisa_bias(h, sqrtf(u1), a, b, c);
        g_tab2[h*TABT + i] = make_float2(t0, t1 - t0);   // (base, delta)
    }
}

// ---------------- prep: convert X inputs to fp16 ----------------
__global__ __launch_bounds__(256) void prep_cvt(const float* __restrict__ x0,
                                                const float* __restrict__ x1,
                                                const float* __restrict__ x2){
    int z = blockIdx.y;
    const float* X = (z == 0) ? x0 : (z == 1) ? x1 : x2;
    unsigned* dh = (unsigned*)&g_sx[z][0];
    const float4* src = (const float4*)X;
    #pragma unroll
    for (int t = 0; t < 2; t++){
        int i4 = blockIdx.x*512 + threadIdx.x + t*256;
        float4 v = src[i4];
        dh[i4*2]   = pack_h2(v.x, v.y);
        dh[i4*2+1] = pack_h2(v.z, v.w);
    }
}

// ---------------- prep: transpose + convert W -> g_wt[n][k] fp16 ----------------
__global__ __launch_bounds__(256) void prep_wt(const float* __restrict__ W0,
                                               const float* __restrict__ W1,
                                               const float* __restrict__ W2,
                                               const float* __restrict__ W3){
    __shared__ float S[64][65];
    int w = blockIdx.z;
    const float* W = (w==0)?W0:(w==1)?W1:(w==2)?W2:W3;
    int k0 = blockIdx.x*64, n0 = blockIdx.y*64, tid = threadIdx.x;
    #pragma unroll
    for (int t = 0; t < 4; t++){
        int i = tid + t*256;
        int row = i >> 4, c4 = i & 15;
        float4 v = *(const float4*)&W[(size_t)(k0+row)*512 + n0 + c4*4];
        S[row][c4*4+0] = v.x; S[row][c4*4+1] = v.y;
        S[row][c4*4+2] = v.z; S[row][c4*4+3] = v.w;
    }
    __syncthreads();
    #pragma unroll
    for (int t = 0; t < 8; t++){
        int i = tid + t*256;
        int n = i >> 5, kp = i & 31;
        unsigned p = pack_h2(S[kp*2][n], S[kp*2+1][n]);
        *(unsigned*)&g_wt[w][(size_t)(n0+n)*512 + k0 + kp*2] = p;
    }
}

// ---------------- single-A GEMM core: tile 128x64, k-chunk 64, 2-stage ----------------
#define G1STAGE 13824
#define GEMM1_SMEM (2*G1STAGE*2)

__device__ __forceinline__ void gemm1_issue(__half* st, int tid, int m0, int n0, int kc,
                                            const __half* Ah, const __half* Wt){
    __half* sX = st;
    __half* sW = st + 9216;
    const int kb = kc*64;
    #pragma unroll
    for (int t = 0; t < 4; t++){
        int i = tid + t*256;
        int row = i >> 3, j = i & 7;
        cp16(sX + row*72 + j*8, Ah + (size_t)(m0+row)*512 + kb + j*8);
    }
    #pragma unroll
    for (int t = 0; t < 2; t++){
        int i = tid + t*256;
        int n = i >> 3, j = i & 7;
        cp16(sW + n*72 + j*8, Wt + (size_t)(n0+n)*512 + kb + j*8);
    }
}

// mode 0: fp32 out; 1: fp16 -> g_qh; 2: fp16 -> g_kh; 3: fp16 transposed -> g_vt
__device__ __forceinline__ void gemm1_core(const __half* __restrict__ Ah,
                                           const __half* __restrict__ Wt,
                                           const float* __restrict__ bias,
                                           int mode, float* __restrict__ out_f,
                                           __half* gsm){
    const int tid  = threadIdx.x;
    const int lane = tid & 31;
    const int warp = tid >> 5;
    const int m0 = blockIdx.x * 128;
    const int n0 = blockIdx.y * 64;
    const int wm = (warp & 3) * 32;
    const int wn = (warp >> 2) * 32;
    const int lr  = lane & 7;
    const int lg1 = (lane >> 3) & 1;
    const int lg2 = (lane >> 4) & 1;

    float acc[2][4][4];
    #pragma unroll
    for (int mt = 0; mt < 2; mt++)
        #pragma unroll
        for (int nt = 0; nt < 4; nt++)
            #pragma unroll
            for (int j = 0; j < 4; j++) acc[mt][nt][j] = 0.f;

    gemm1_issue(gsm, tid, m0, n0, 0, Ah, Wt);
    CP_COMMIT();

    for (int kc = 0; kc < 8; kc++){
        if (kc + 1 < 8){
            gemm1_issue(gsm + ((kc+1)&1)*G1STAGE, tid, m0, n0, kc+1, Ah, Wt);
            CP_COMMIT();
            CP_WAIT1();
        } else {
            CP_WAIT0();
        }
        __syncthreads();

        __half* sX = gsm + (kc&1)*G1STAGE;
        __half* sW = sX + 9216;

        #pragma unroll
        for (int ks = 0; ks < 4; ks++){
            unsigned aH[2][4];
            #pragma unroll
            for (int mt = 0; mt < 2; mt++){
                int ao = (wm + mt*16 + lr + lg1*8)*72 + ks*16 + lg2*8;
                ldsm4(aH[mt], sX + ao);
            }
            unsigned bb[2][4];
            ldsm4(bb[0], sW + (wn      + lr + lg2*8)*72 + ks*16 + lg1*8);
            ldsm4(bb[1], sW + (wn + 16 + lr + lg2*8)*72 + ks*16 + lg1*8);
            #pragma unroll
            for (int nt = 0; nt < 4; nt++){
                const unsigned* bH = &bb[nt>>1][(nt&1)*2];
                #pragma unroll
                for (int mt = 0; mt < 2; mt++)
                    mma_f16(acc[mt][nt], aH[mt], bH);
            }
        }
        __syncthreads();
    }

    #pragma unroll
    for (int mt = 0; mt < 2; mt++)
        #pragma unroll
        for (int nt = 0; nt < 4; nt++){
            int r = m0 + wm + mt*16 + (lane>>2);
            int c = n0 + wn + nt*8 + (lane&3)*2;
            float b0 = bias[c], b1 = bias[c+1];
            float v00 = acc[mt][nt][0] + b0, v01 = acc[mt][nt][1] + b1;
            float v10 = acc[mt][nt][2] + b0, v11 = acc[mt][nt][3] + b1;
            if (mode == 0){
                *(float2*)&out_f[(size_t)r*512 + c]     = make_float2(v00, v01);
                *(float2*)&out_f[(size_t)(r+8)*512 + c] = make_float2(v10, v11);
            } else if (mode == 1){
                *(unsigned*)&g_qh[(size_t)r*512 + c]     = pack_h2(v00, v01);
                *(unsigned*)&g_qh[(size_t)(r+8)*512 + c] = pack_h2(v10, v11);
            } else if (mode == 2){
                *(unsigned*)&g_kh[(size_t)r*512 + c]     = pack_h2(v00, v01);
                *(unsigned*)&g_kh[(size_t)(r+8)*512 + c] = pack_h2(v10, v11);
            } else {
                int bidx = r >> 11;
                int key  = r & 2047;
                int d    = c & 63;
                size_t vbase = ((size_t)(bidx*8 + blockIdx.y))*64;
                g_vt[(vbase + d  )*2048 + key]     = __float2half_rn(v00);
                g_vt[(vbase + d+1)*2048 + key]     = __float2half_rn(v01);
                g_vt[(vbase + d  )*2048 + key + 8] = __float2half_rn(v10);
                g_vt[(vbase + d+1)*2048 + key + 8] = __float2half_rn(v11);
            }
        }
}

__global__ __launch_bounds__(256) void gemm_qkv(const float* bq, const float* bk, const float* bv){
    extern __shared__ __half gsm[];
    const int z = blockIdx.z;
    const float* bias = (z==0) ? bq : (z==1) ? bk : bv;
    gemm1_core(g_sx[z], g_wt[z], bias, z+1, nullptr, gsm);
}
__global__ __launch_bounds__(256) void gemm_o(const float* bo, float* out){
    extern __shared__ __half gsm[];
    gemm1_core(g_ct, g_wt[3], bo, 0, out, gsm);
}

// ---------------- fused flash attention: 2 key-split warp groups, fixed-offset softmax ----------------
// smem: klb float[2][2][128] | Qh half[128*72] | KV: per group {K[2][64*72], V[2][64*72]}
#define ATTN_SMEM (4*128*4 + 128*72*2 + 8*64*72*2)

__device__ __forceinline__ void attn_issue(__half* Ks, __half* Vs, float* klb,
                                           int gtid, int b, int h, int k0,
                                           const float* __restrict__ klocs){
    #pragma unroll
    for (int t = 0; t < 2; t++){
        int i = gtid + t*256;
        int row = i >> 3, j = i & 7;
        cp16(Ks + row*72 + j*8, g_kh + (size_t)(b*Kq + k0 + row)*512 + h*64 + j*8);
    }
    #pragma unroll
    for (int t = 0; t < 2; t++){
        int i = gtid + t*256;
        int d = i >> 3, j = i & 7;
        cp16(Vs + d*72 + j*8, g_vt + ((size_t)(b*8 + h)*64 + d)*2048 + k0 + j*8);
    }
    if (gtid < 32) cp16(klb + gtid*4, klocs + (size_t)(b*Kq + k0)*2 + gtid*4);
}

__global__ __launch_bounds__(512, 2) void attn_kernel(const float* __restrict__ qlocs,
                                                      const float* __restrict__ klocs,
                                                      const int* __restrict__ vlens){
    extern __shared__ char smem[];
    float*  klb = (float*)smem;               // [2 grp][2 st][128]
    __half* Qh  = (__half*)(klb + 512);
    __half* KV  = Qh + 128*72;

    const int tid  = threadIdx.x;
    const int grp  = tid >> 8;                // 0 or 1
    const int gtid = tid & 255;
    const int lane = tid & 31;
    const int warp = gtid >> 5;               // 0..7 within group
    const int qt = blockIdx.x * 128;
    const int h  = blockIdx.y;
    const int b  = blockIdx.z;
    const int lr  = lane & 7;
    const int lg1 = (lane >> 3) & 1;
    const int lg2 = (lane >> 4) & 1;

    __half* Kg  = KV + grp*18432;
    __half* Vg  = Kg + 9216;
    float*  klg = klb + grp*256;

    const int vl = vlens[b];
    const int nch = (vl + 63) >> 6;
    const float2* __restrict__ tabh = g_tab2 + h*TABT;

    // commit group #0: Q tile (all 512 threads cooperate)
    #pragma unroll
    for (int t = 0; t < 2; t++){
        int i = tid + t*512;
        int row = i >> 3, j = i & 7;
        cp16(Qh + row*72 + j*8, g_qh + (size_t)(b*Qq + qt + row)*512 + h*64 + j*8);
    }
    CP_COMMIT();
    // commit group #1: this group's first chunk
    if (grp < nch) attn_issue(Kg, Vg, klg, gtid, b, h, grp*64, klocs);
    CP_COMMIT();
    CP_WAIT1();        // Q tile done (per thread)
    __syncthreads();   // Q tile visible block-wide

    const int r0 = warp*16 + (lane>>2);
    float qx0 = qlocs[((size_t)(b*Qq + qt + r0))*2 + 0];
    float qy0 = qlocs[((size_t)(b*Qq + qt + r0))*2 + 1];
    float qx1 = qlocs[((size_t)(b*Qq + qt + r0 + 8))*2 + 0];
    float qy1 = qlocs[((size_t)(b*Qq + qt + r0 + 8))*2 + 1];

    const float FSC = (float)(TABF-1);
    const float CSC = (float)(TABC-1)/U_COARSE_MAX;
    const float SC  = 0.125f * LOG2E;

    float l0 = 0.f, l1 = 0.f;
    float o[8][4];
    #pragma unroll
    for (int n = 0; n < 8; n++){ o[n][0]=0.f; o[n][1]=0.f; o[n][2]=0.f; o[n][3]=0.f; }

    int ci = 0;
    for (int kc = grp; kc < nch; kc += 2, ci++){
        if (kc + 2 < nch){
            int st = (ci+1) & 1;
            attn_issue(Kg + st*4608, Vg + st*4608, klg + st*128, gtid, b, h, (kc+2)*64, klocs);
            CP_COMMIT();
            CP_WAIT1();
        } else {
            CP_WAIT0();
        }
        GRP_BAR(grp);

        const int st = ci & 1;
        const __half* sK = Kg + st*4608;
        const __half* sV = Vg + st*4608;
        const float2* kl2 = (const float2*)(klg + st*128);
        const int k0 = kc * 64;

        float s[8][4];
        #pragma unroll
        for (int n = 0; n < 8; n++){ s[n][0]=0.f; s[n][1]=0.f; s[n][2]=0.f; s[n][3]=0.f; }

        #pragma unroll
        for (int ks = 0; ks < 4; ks++){
            unsigned aH[4];
            int ao = (warp*16 + lr + lg1*8)*72 + ks*16 + lg2*8;
            ldsm4(aH, Qh + ao);
            unsigned bk4[4][4];
            #pragma unroll
            for (int g = 0; g < 4; g++)
                ldsm4(bk4[g], sK + (g*16 + lr + lg2*8)*72 + ks*16 + lg1*8);
            #pragma unroll
            for (int n = 0; n < 8; n++){
                const unsigned* bH = &bk4[n>>1][(n&1)*2];
                mma_f16(s[n], aH, bH);
            }
        }

        // bias (offset folded in) via global L1-cached (t0, delta) lerp table
        #pragma unroll
        for (int n = 0; n < 8; n++){
            #pragma unroll
            for (int j = 0; j < 2; j++){
                int kkl = n*8 + (lane&3)*2 + j;
                float2 kxy = kl2[kkl];

                float dx = qx0 - kxy.x, dy = qy0 - kxy.y;
                float u = fmaf(dx, dx, dy*dy);
                bool fine = (u < 1.0f);
                float fi = fine ? u*FSC : u*CSC;
                int ti = (int)fi;
                float w = fi - (float)ti;
                float2 tv = __ldg(&tabh[(fine ? 0 : TABF) + ti]);
                s[n][j] = fmaf(s[n][j], SC, fmaf(w, tv.y, tv.x));

                dx = qx1 - kxy.x; dy = qy1 - kxy.y;
                u = fmaf(dx, dx, dy*dy);
                fine = (u < 1.0f);
                fi = fine ? u*FSC : u*CSC;
                ti = (int)fi;
                w = fi - (float)ti;
                tv = __ldg(&tabh[(fine ? 0 : TABF) + ti]);
                s[n][2+j] = fmaf(s[n][2+j], SC, fmaf(w, tv.y, tv.x));
            }
        }

        // mask fix-up: only on the (at most one) partial chunk
        if (k0 + 64 > vl){
            #pragma unroll
            for (int n = 0; n < 8; n++){
                int kk0 = k0 + n*8 + (lane&3)*2;
                if (kk0     >= vl){ s[n][0] = -1e30f; s[n][2] = -1e30f; }
                if (kk0 + 1 >= vl){ s[n][1] = -1e30f; s[n][3] = -1e30f; }
            }
        }

        // P = 2^s; accumulate l
        #pragma unroll
        for (int n = 0; n < 8; n++){
            s[n][0] = ex2f(s[n][0]);
            s[n][1] = ex2f(s[n][1]);
            s[n][2] = ex2f(s[n][2]);
            s[n][3] = ex2f(s[n][3]);
            l0 += s[n][0] + s[n][1];
            l1 += s[n][2] + s[n][3];
        }

        // O += P V
        #pragma unroll
        for (int kk = 0; kk < 4; kk++){
            unsigned aH[4];
            aH[0] = pack_h2(s[2*kk][0],   s[2*kk][1]);
            aH[1] = pack_h2(s[2*kk][2],   s[2*kk][3]);
            aH[2] = pack_h2(s[2*kk+1][0], s[2*kk+1][1]);
            aH[3] = pack_h2(s[2*kk+1][2], s[2*kk+1][3]);
            unsigned bv4[4][4];
            #pragma unroll
            for (int g = 0; g < 4; g++)
                ldsm4(bv4[g], sV + (g*16 + lr + lg2*8)*72 + kk*16 + lg1*8);
            #pragma unroll
            for (int n = 0; n < 8; n++){
                const unsigned* bH = &bv4[n>>1][(n&1)*2];
                mma_f16(o[n], aH, bH);
            }
        }
        GRP_BAR(grp);
    }

    // quad-reduce partial l within each group
    l0 += __shfl_xor_sync(0xffffffffu, l0, 1);
    l0 += __shfl_xor_sync(0xffffffffu, l0, 2);
    l1 += __shfl_xor_sync(0xffffffffu, l1, 1);
    l1 += __shfl_xor_sync(0xffffffffu, l1, 2);

    // merge the two groups' partials (exact: fixed-offset softmax -> plain sums)
    __syncthreads();
    float* mo = (float*)KV;    // overlay merge buffer: 256 threads x 34 floats
    if (grp == 1){
        float* dst = mo + gtid*34;
        #pragma unroll
        for (int n = 0; n < 8; n++){
            dst[n*4+0] = o[n][0]; dst[n*4+1] = o[n][1];
            dst[n*4+2] = o[n][2]; dst[n*4+3] = o[n][3];
        }
        dst[32] = l0; dst[33] = l1;
    }
    __syncthreads();
    if (grp == 0){
        const float* src = mo + gtid*34;
        #pragma unroll
        for (int n = 0; n < 8; n++){
            o[n][0] += src[n*4+0]; o[n][1] += src[n*4+1];
            o[n][2] += src[n*4+2]; o[n][3] += src[n*4+3];
        }
        l0 += src[32]; l1 += src[33];
        float inv0 = 1.f / l0, inv1 = 1.f / l1;
        #pragma unroll
        for (int n = 0; n < 8; n++){
            int c = h*DHh + n*8 + (lane&3)*2;
            size_t r = (size_t)(b*Qq + qt + warp*16 + (lane>>2));
            *(unsigned*)&g_ct[r*512 + c]     = pack_h2(o[n][0]*inv0, o[n][1]*inv0);
            *(unsigned*)&g_ct[(r+8)*512 + c] = pack_h2(o[n][2]*inv1, o[n][3]*inv1);
        }
    }
}

// ---------------- launch ----------------
extern "C" void kernel_launch(void* const* d_in, const int* in_sizes, int n_in,
                              void* d_out, int out_size){
    (void)in_sizes; (void)n_in; (void)out_size;
    const float* qs    = (const float*)d_in[0];
    const float* ks    = (const float*)d_in[1];
    const float* vs    = (const float*)d_in[2];
    const float* qlocs = (const float*)d_in[3];
    const float* klocs = (const float*)d_in[4];
    const float* Wq    = (const float*)d_in[5];
    const float* bq    = (const float*)d_in[6];
    const float* Wk    = (const float*)d_in[7];
    const float* bk    = (const float*)d_in[8];
    const float* Wv    = (const float*)d_in[9];
    const float* bv    = (const float*)d_in[10];
    const float* Wo    = (const float*)d_in[11];
    const float* bo    = (const float*)d_in[12];
    const float* pa    = (const float*)d_in[13];
    const float* pb    = (const float*)d_in[14];
    const float* pc    = (const float*)d_in[15];
    const int*   vlens = (const int*)d_in[16];

    cudaFuncSetAttribute(gemm_qkv,    cudaFuncAttributeMaxDynamicSharedMemorySize, GEMM1_SMEM);
    cudaFuncSetAttribute(gemm_o,      cudaFuncAttributeMaxDynamicSharedMemorySize, GEMM1_SMEM);
    cudaFuncSetAttribute(attn_kernel, cudaFuncAttributeMaxDynamicSharedMemorySize, ATTN_SMEM);

    build_tab_kernel<<<Hh, 256>>>(pa, pb, pc);
    prep_cvt<<<dim3(1024, 3), 256>>>(qs, ks, vs);
    prep_wt<<<dim3(8, 8, 4), 256>>>(Wq, Wk, Wv, Wo);

    gemm_qkv<<<dim3(32, 8, 3), 256, GEMM1_SMEM>>>(bq, bk, bv);

    attn_kernel<<<dim3(16, 8, 2), 512, ATTN_SMEM>>>(qlocs, klocs, vlens);

    gemm_o<<<dim3(32, 8), 256, GEMM1_SMEM>>>(bo, (float*)d_out);
}

// round 15
// speedup vs baseline: 2.6409x; 2.6409x over previous
#include <cuda_runtime.h>
#include <cuda_fp16.h>

#define Bb 2
#define Qq 2048
#define Kq 2048
#define DMm 512
#define Hh 8
#define Ff 5
#define DHh 64
#define LOG2E 1.4426950408889634f
#define M0OFF 12.0f   // fixed softmax offset (folded into bias table)

// bias table: d^2-indexed, LERP, float2 pairs (t_i, t_{i+1}); stores bias*LOG2E - M0OFF
#define TABF 1024
#define TABC 4096
#define TABT (TABF + TABC)
#define U_COARSE_MAX 202.0f

// ---------------- scratch (__device__ globals; no allocation allowed) ----------------
__device__ __half g_sx[3][Bb*Qq*DMm];    // qs/ks/vs converted to fp16
__device__ __half g_wt[4][DMm*DMm];      // W transposed [n][k], fp16
__device__ __half g_qh[Bb*Qq*DMm];       // projected Q fp16
__device__ __half g_kh[Bb*Kq*DMm];       // projected K fp16
__device__ __half g_vt[Bb*Hh*DHh*Kq];    // projected V fp16, transposed [b][h][d][key]
__device__ __half g_ct[Bb*Qq*DMm];       // ctx fp16
__device__ float2 g_tab2[Hh*TABT];       // (bias*LOG2E - M0)[i], [i+1] pairs

// ---------------- helpers ----------------
__device__ __forceinline__ unsigned pack_h2(float a, float b){
    __half2 h = __floats2half2_rn(a, b);
    return *reinterpret_cast<unsigned*>(&h);
}
__device__ __forceinline__ void mma_f16(float c[4], const unsigned a[4], const unsigned b[2]){
    asm volatile(
        "mma.sync.aligned.m16n8k16.row.col.f32.f16.f16.f32 "
        "{%0,%1,%2,%3},{%4,%5,%6,%7},{%8,%9},{%0,%1,%2,%3};\n"
        : "+f"(c[0]), "+f"(c[1]), "+f"(c[2]), "+f"(c[3])
        : "r"(a[0]), "r"(a[1]), "r"(a[2]), "r"(a[3]), "r"(b[0]), "r"(b[1]));
}
__device__ __forceinline__ void ldsm4(unsigned r[4], const __half* p){
    unsigned a = (unsigned)__cvta_generic_to_shared(p);
    asm volatile("ldmatrix.sync.aligned.m8n8.x4.shared.b16 {%0,%1,%2,%3}, [%4];\n"
        : "=r"(r[0]), "=r"(r[1]), "=r"(r[2]), "=r"(r[3]) : "r"(a));
}
__device__ __forceinline__ float ex2f(float x){
    float y; asm("ex2.approx.f32 %0, %1;" : "=f"(y) : "f"(x)); return y;
}
__device__ __forceinline__ void cp16(void* sdst, const void* gsrc){
    unsigned s = (unsigned)__cvta_generic_to_shared(sdst);
    asm volatile("cp.async.cg.shared.global [%0], [%1], 16;\n" :: "r"(s), "l"(gsrc));
}
#define CP_COMMIT() asm volatile("cp.async.commit_group;\n" ::: "memory")
#define CP_WAIT0()  asm volatile("cp.async.wait_group 0;\n" ::: "memory")
#define CP_WAIT1()  asm volatile("cp.async.wait_group 1;\n" ::: "memory")

// ---------------- bias table ----------------
__device__ __forceinline__ float tisa_bias(int h, float d,
                                           const float* a, const float* b, const float* c){
    float s = 0.f;
    #pragma unroll
    for (int f = 0; f < Ff; f++){
        float af = a[h*Ff + f];
        float bf = fabsf(b[h*Ff + f]);
        float cf = c[h*Ff + f];
        float t  = d - cf;
        s += af * expf(-bf * t * t);
    }
    return s * LOG2E - M0OFF;   // fixed softmax offset folded in
}

__global__ void build_tab_kernel(const float* __restrict__ a,
                                 const float* __restrict__ b,
                                 const float* __restrict__ c){
    int h = blockIdx.x;
    for (int i = threadIdx.x; i < TABT; i += blockDim.x){
        float u0, u1;
        if (i < TABF){
            u0 = (float)i     * (1.0f/(TABF-1));
            u1 = (float)(i+1) * (1.0f/(TABF-1));
        } else {
            u0 = (float)(i - TABF)     * (U_COARSE_MAX/(TABC-1));
            u1 = (float)(i - TABF + 1) * (U_COARSE_MAX/(TABC-1));
        }
        float t0 = tisa_bias(h, sqrtf(u0), a, b, c);
        float t1 = tisa_bias(h, sqrtf(u1), a, b, c);
        g_tab2[h*TABT + i] = make_float2(t0, t1);
    }
}

// ---------------- prep: convert X inputs to fp16 ----------------
__global__ __launch_bounds__(256) void prep_cvt(const float* __restrict__ x0,
                                                const float* __restrict__ x1,
                                                const float* __restrict__ x2){
    int z = blockIdx.y;
    const float* X = (z == 0) ? x0 : (z == 1) ? x1 : x2;
    unsigned* dh = (unsigned*)&g_sx[z][0];
    const float4* src = (const float4*)X;
    #pragma unroll
    for (int t = 0; t < 2; t++){
        int i4 = blockIdx.x*512 + threadIdx.x + t*256;
        float4 v = src[i4];
        dh[i4*2]   = pack_h2(v.x, v.y);
        dh[i4*2+1] = pack_h2(v.z, v.w);
    }
}

// ---------------- prep: transpose + convert W -> g_wt[n][k] fp16 ----------------
__global__ __launch_bounds__(256) void prep_wt(const float* __restrict__ W0,
                                               const float* __restrict__ W1,
                                               const float* __restrict__ W2,
                                               const float* __restrict__ W3){
    __shared__ float S[64][65];
    int w = blockIdx.z;
    const float* W = (w==0)?W0:(w==1)?W1:(w==2)?W2:W3;
    int k0 = blockIdx.x*64, n0 = blockIdx.y*64, tid = threadIdx.x;
    #pragma unroll
    for (int t = 0; t < 4; t++){
        int i = tid + t*256;
        int row = i >> 4, c4 = i & 15;
        float4 v = *(const float4*)&W[(size_t)(k0+row)*512 + n0 + c4*4];
        S[row][c4*4+0] = v.x; S[row][c4*4+1] = v.y;
        S[row][c4*4+2] = v.z; S[row][c4*4+3] = v.w;
    }
    __syncthreads();
    #pragma unroll
    for (int t = 0; t < 8; t++){
        int i = tid + t*256;
        int n = i >> 5, kp = i & 31;
        unsigned p = pack_h2(S[kp*2][n], S[kp*2+1][n]);
        *(unsigned*)&g_wt[w][(size_t)(n0+n)*512 + k0 + kp*2] = p;
    }
}

// ---------------- single-A GEMM core: tile 128x128, k-chunk 64, 2-stage ----------------
#define G1STAGE 18432
#define GEMM1_SMEM (2*G1STAGE*2)

__device__ __forceinline__ void gemm1_issue(__half* st, int tid, int m0, int n0, int kc,
                                            const __half* Ah, const __half* Wt){
    __half* sX = st;
    __half* sW = st + 9216;
    const int kb = kc*64;
    #pragma unroll
    for (int t = 0; t < 4; t++){
        int i = tid + t*256;
        int row = i >> 3, j = i & 7;
        cp16(sX + row*72 + j*8, Ah + (size_t)(m0+row)*512 + kb + j*8);
        cp16(sW + row*72 + j*8, Wt + (size_t)(n0+row)*512 + kb + j*8);
    }
}

// mode 0: fp32 out; 1: fp16 -> g_qh; 2: fp16 -> g_kh; 3: fp16 transposed -> g_vt
__device__ __forceinline__ void gemm1_core(const __half* __restrict__ Ah,
                                           const __half* __restrict__ Wt,
                                           const float* __restrict__ bias,
                                           int mode, float* __restrict__ out_f,
                                           __half* gsm){
    const int tid  = threadIdx.x;
    const int lane = tid & 31;
    const int warp = tid >> 5;
    const int m0 = blockIdx.x * 128;
    const int n0 = blockIdx.y * 128;
    const int wm = (warp & 3) * 32;
    const int wn = (warp >> 2) * 64;
    const int lr  = lane & 7;
    const int lg1 = (lane >> 3) & 1;
    const int lg2 = (lane >> 4) & 1;

    float acc[2][8][4];
    #pragma unroll
    for (int mt = 0; mt < 2; mt++)
        #pragma unroll
        for (int nt = 0; nt < 8; nt++)
            #pragma unroll
            for (int j = 0; j < 4; j++) acc[mt][nt][j] = 0.f;

    gemm1_issue(gsm, tid, m0, n0, 0, Ah, Wt);
    CP_COMMIT();

    for (int kc = 0; kc < 8; kc++){
        if (kc + 1 < 8){
            gemm1_issue(gsm + ((kc+1)&1)*G1STAGE, tid, m0, n0, kc+1, Ah, Wt);
            CP_COMMIT();
            CP_WAIT1();
        } else {
            CP_WAIT0();
        }
        __syncthreads();

        __half* sX = gsm + (kc&1)*G1STAGE;
        __half* sW = sX + 9216;

        #pragma unroll
        for (int ks = 0; ks < 4; ks++){
            unsigned aH[2][4];
            #pragma unroll
            for (int mt = 0; mt < 2; mt++){
                int ao = (wm + mt*16 + lr + lg1*8)*72 + ks*16 + lg2*8;
                ldsm4(aH[mt], sX + ao);
            }
            unsigned bb[4][4];
            #pragma unroll
            for (int g = 0; g < 4; g++)
                ldsm4(bb[g], sW + (wn + g*16 + lr + lg2*8)*72 + ks*16 + lg1*8);
            #pragma unroll
            for (int nt = 0; nt < 8; nt++){
                const unsigned* bH = &bb[nt>>1][(nt&1)*2];
                #pragma unroll
                for (int mt = 0; mt < 2; mt++)
                    mma_f16(acc[mt][nt], aH[mt], bH);
            }
        }
        __syncthreads();
    }

    #pragma unroll
    for (int mt = 0; mt < 2; mt++)
        #pragma unroll
        for (int nt = 0; nt < 8; nt++){
            int r = m0 + wm + mt*16 + (lane>>2);
            int c = n0 + wn + nt*8 + (lane&3)*2;
            float b0 = bias[c], b1 = bias[c+1];
            float v00 = acc[mt][nt][0] + b0, v01 = acc[mt][nt][1] + b1;
            float v10 = acc[mt][nt][2] + b0, v11 = acc[mt][nt][3] + b1;
            if (mode == 0){
                *(float2*)&out_f[(size_t)r*512 + c]     = make_float2(v00, v01);
                *(float2*)&out_f[(size_t)(r+8)*512 + c] = make_float2(v10, v11);
            } else if (mode == 1){
                *(unsigned*)&g_qh[(size_t)r*512 + c]     = pack_h2(v00, v01);
                *(unsigned*)&g_qh[(size_t)(r+8)*512 + c] = pack_h2(v10, v11);
            } else if (mode == 2){
                *(unsigned*)&g_kh[(size_t)r*512 + c]     = pack_h2(v00, v01);
                *(unsigned*)&g_kh[(size_t)(r+8)*512 + c] = pack_h2(v10, v11);
            } else {
                int bidx = r >> 11;
                int key  = r & 2047;
                int d    = c & 63;
                int hh   = c >> 6;
                size_t vbase = ((size_t)(bidx*8 + hh))*64;
                g_vt[(vbase + d  )*2048 + key]     = __float2half_rn(v00);
                g_vt[(vbase + d+1)*2048 + key]     = __float2half_rn(v01);
                g_vt[(vbase + d  )*2048 + key + 8] = __float2half_rn(v10);
                g_vt[(vbase + d+1)*2048 + key + 8] = __float2half_rn(v11);
            }
        }
}

__global__ __launch_bounds__(256) void gemm_qkv(const float* bq, const float* bk, const float* bv){
    extern __shared__ __half gsm[];
    const int z = blockIdx.z;
    const float* bias = (z==0) ? bq : (z==1) ? bk : bv;
    gemm1_core(g_sx[z], g_wt[z], bias, z+1, nullptr, gsm);
}
__global__ __launch_bounds__(256) void gemm_o(const float* bo, float* out){
    extern __shared__ __half gsm[];
    gemm1_core(g_ct, g_wt[3], bo, 0, out, gsm);
}

// ---------------- fused flash attention (fixed-offset softmax) — R13-proven ----------------
// smem: stab2 float2[TABT] (40KB) | klb[2][128]f | Qh [128*72] | Ks[2][64*72] | Vs[2][64*72]
#define ATTN_SMEM (TABT*8 + 2*128*4 + 128*72*2 + 4*(64*72*2))

__device__ __forceinline__ void attn_issue(__half* Ks, __half* Vs, float* klb,
                                           int tid, int b, int h, int k0,
                                           const float* __restrict__ klocs){
    #pragma unroll
    for (int t = 0; t < 2; t++){
        int i = tid + t*256;
        int row = i >> 3, j = i & 7;
        cp16(Ks + row*72 + j*8, g_kh + (size_t)(b*Kq + k0 + row)*512 + h*64 + j*8);
    }
    #pragma unroll
    for (int t = 0; t < 2; t++){
        int i = tid + t*256;
        int d = i >> 3, j = i & 7;
        cp16(Vs + d*72 + j*8, g_vt + ((size_t)(b*8 + h)*64 + d)*2048 + k0 + j*8);
    }
    if (tid < 32) cp16(klb + tid*4, klocs + (size_t)(b*Kq + k0)*2 + tid*4);
}

__global__ __launch_bounds__(256, 2) void attn_kernel(const float* __restrict__ qlocs,
                                                      const float* __restrict__ klocs,
                                                      const int* __restrict__ vlens){
    extern __shared__ char smem[];
    float2* stab2 = (float2*)smem;
    float*  klb   = (float*)(stab2 + TABT);
    __half* Qh = (__half*)(klb + 256);
    __half* Ks = Qh + 128*72;
    __half* Vs = Ks + 2*64*72;

    const int tid  = threadIdx.x;
    const int lane = tid & 31;
    const int warp = tid >> 5;
    const int qt = blockIdx.x * 128;
    const int h  = blockIdx.y;
    const int b  = blockIdx.z;
    const int lr  = lane & 7;
    const int lg1 = (lane >> 3) & 1;
    const int lg2 = (lane >> 4) & 1;

    const int vl = vlens[b];
    const int nch = (vl + 63) >> 6;

    #pragma unroll
    for (int t = 0; t < 4; t++){
        int i = tid + t*256;
        int row = i >> 3, j = i & 7;
        cp16(Qh + row*72 + j*8, g_qh + (size_t)(b*Qq + qt + row)*512 + h*64 + j*8);
    }
    attn_issue(Ks, Vs, klb, tid, b, h, 0, klocs);
    CP_COMMIT();

    for (int i = tid; i < TABT; i += 256) stab2[i] = g_tab2[h*TABT + i];

    const int r0 = warp*16 + (lane>>2);
    float qx0 = qlocs[((size_t)(b*Qq + qt + r0))*2 + 0];
    float qy0 = qlocs[((size_t)(b*Qq + qt + r0))*2 + 1];
    float qx1 = qlocs[((size_t)(b*Qq + qt + r0 + 8))*2 + 0];
    float qy1 = qlocs[((size_t)(b*Qq + qt + r0 + 8))*2 + 1];

    const float FSC = (float)(TABF-1);
    const float CSC = (float)(TABC-1)/U_COARSE_MAX;
    const float SC  = 0.125f * LOG2E;

    float l0 = 0.f, l1 = 0.f;
    float o[8][4];
    #pragma unroll
    for (int n = 0; n < 8; n++){ o[n][0]=0.f; o[n][1]=0.f; o[n][2]=0.f; o[n][3]=0.f; }

    for (int kc = 0; kc < nch; kc++){
        if (kc + 1 < nch){
            int st = (kc+1) & 1;
            attn_issue(Ks + st*64*72, Vs + st*64*72, klb + st*128, tid, b, h, (kc+1)*64, klocs);
            CP_COMMIT();
            CP_WAIT1();
        } else {
            CP_WAIT0();
        }
        __syncthreads();

        const int st = kc & 1;
        const __half* sK = Ks + st*64*72;
        const __half* sV = Vs + st*64*72;
        const float2* kl2 = (const float2*)(klb + st*128);
        const int k0 = kc * 64;

        float s[8][4];
        #pragma unroll
        for (int n = 0; n < 8; n++){ s[n][0]=0.f; s[n][1]=0.f; s[n][2]=0.f; s[n][3]=0.f; }

        #pragma unroll
        for (int ks = 0; ks < 4; ks++){
            unsigned aH[4];
            int ao = (warp*16 + lr + lg1*8)*72 + ks*16 + lg2*8;
            ldsm4(aH, Qh + ao);
            unsigned bk4[4][4];
            #pragma unroll
            for (int g = 0; g < 4; g++)
                ldsm4(bk4[g], sK + (g*16 + lr + lg2*8)*72 + ks*16 + lg1*8);
            #pragma unroll
            for (int n = 0; n < 8; n++){
                const unsigned* bH = &bk4[n>>1][(n&1)*2];
                mma_f16(s[n], aH, bH);
            }
        }

        // bias (fixed softmax offset folded in) + lerp table
        #pragma unroll
        for (int n = 0; n < 8; n++){
            #pragma unroll
            for (int j = 0; j < 2; j++){
                int kkl = n*8 + (lane&3)*2 + j;
                float2 kxy = kl2[kkl];

                float dx = qx0 - kxy.x, dy = qy0 - kxy.y;
                float u = fmaf(dx, dx, dy*dy);
                bool fine = (u < 1.0f);
                float fi = fine ? u*FSC : u*CSC;
                int ti = (int)fi;
                float w = fi - (float)ti;
                float2 tv = stab2[(fine ? 0 : TABF) + ti];
                s[n][j] = fmaf(s[n][j], SC, fmaf(w, tv.y - tv.x, tv.x));

                dx = qx1 - kxy.x; dy = qy1 - kxy.y;
                u = fmaf(dx, dx, dy*dy);
                fine = (u < 1.0f);
                fi = fine ? u*FSC : u*CSC;
                ti = (int)fi;
                w = fi - (float)ti;
                tv = stab2[(fine ? 0 : TABF) + ti];
                s[n][2+j] = fmaf(s[n][2+j], SC, fmaf(w, tv.y - tv.x, tv.x));
            }
        }

        // mask fix-up: only on the (at most one) partial chunk
        if (k0 + 64 > vl){
            #pragma unroll
            for (int n = 0; n < 8; n++){
                int kk0 = k0 + n*8 + (lane&3)*2;
                if (kk0     >= vl){ s[n][0] = -1e30f; s[n][2] = -1e30f; }
                if (kk0 + 1 >= vl){ s[n][1] = -1e30f; s[n][3] = -1e30f; }
            }
        }

        // P = 2^s; accumulate l
        #pragma unroll
        for (int n = 0; n < 8; n++){
            s[n][0] = ex2f(s[n][0]);
            s[n][1] = ex2f(s[n][1]);
            s[n][2] = ex2f(s[n][2]);
            s[n][3] = ex2f(s[n][3]);
            l0 += s[n][0] + s[n][1];
            l1 += s[n][2] + s[n][3];
        }

        // O += P V
        #pragma unroll
        for (int kk = 0; kk < 4; kk++){
            unsigned aH[4];
            aH[0] = pack_h2(s[2*kk][0],   s[2*kk][1]);
            aH[1] = pack_h2(s[2*kk][2],   s[2*kk][3]);
            aH[2] = pack_h2(s[2*kk+1][0], s[2*kk+1][1]);
            aH[3] = pack_h2(s[2*kk+1][2], s[2*kk+1][3]);
            unsigned bv4[4][4];
            #pragma unroll
            for (int g = 0; g < 4; g++)
                ldsm4(bv4[g], sV + (g*16 + lr + lg2*8)*72 + kk*16 + lg1*8);
            #pragma unroll
            for (int n = 0; n < 8; n++){
                const unsigned* bH = &bv4[n>>1][(n&1)*2];
                mma_f16(o[n], aH, bH);
            }
        }
        __syncthreads();
    }

    l0 += __shfl_xor_sync(0xffffffffu, l0, 1);
    l0 += __shfl_xor_sync(0xffffffffu, l0, 2);
    l1 += __shfl_xor_sync(0xffffffffu, l1, 1);
    l1 += __shfl_xor_sync(0xffffffffu, l1, 2);
    float inv0 = 1.f / l0, inv1 = 1.f / l1;

    #pragma unroll
    for (int n = 0; n < 8; n++){
        int c = h*DHh + n*8 + (lane&3)*2;
        size_t r = (size_t)(b*Qq + qt + warp*16 + (lane>>2));
        *(unsigned*)&g_ct[r*512 + c]     = pack_h2(o[n][0]*inv0, o[n][1]*inv0);
        *(unsigned*)&g_ct[(r+8)*512 + c] = pack_h2(o[n][2]*inv1, o[n][3]*inv1);
    }
}

// ---------------- launch ----------------
extern "C" void kernel_launch(void* const* d_in, const int* in_sizes, int n_in,
                              void* d_out, int out_size){
    (void)in_sizes; (void)n_in; (void)out_size;
    const float* qs    = (const float*)d_in[0];
    const float* ks    = (const float*)d_in[1];
    const float* vs    = (const float*)d_in[2];
    const float* qlocs = (const float*)d_in[3];
    const float* klocs = (const float*)d_in[4];
    const float* Wq    = (const float*)d_in[5];
    const float* bq    = (const float*)d_in[6];
    const float* Wk    = (const float*)d_in[7];
    const float* bk    = (const float*)d_in[8];
    const float* Wv    = (const float*)d_in[9];
    const float* bv    = (const float*)d_in[10];
    const float* Wo    = (const float*)d_in[11];
    const float* bo    = (const float*)d_in[12];
    const float* pa    = (const float*)d_in[13];
    const float* pb    = (const float*)d_in[14];
    const float* pc    = (const float*)d_in[15];
    const int*   vlens = (const int*)d_in[16];

    cudaFuncSetAttribute(gemm_qkv,    cudaFuncAttributeMaxDynamicSharedMemorySize, GEMM1_SMEM);
    cudaFuncSetAttribute(gemm_o,      cudaFuncAttributeMaxDynamicSharedMemorySize, GEMM1_SMEM);
    cudaFuncSetAttribute(attn_kernel, cudaFuncAttributeMaxDynamicSharedMemorySize, ATTN_SMEM);

    build_tab_kernel<<<Hh, 256>>>(pa, pb, pc);
    prep_cvt<<<dim3(1024, 3), 256>>>(qs, ks, vs);
    prep_wt<<<dim3(8, 8, 4), 256>>>(Wq, Wk, Wv, Wo);

    gemm_qkv<<<dim3(32, 4, 3), 256, GEMM1_SMEM>>>(bq, bk, bv);

    attn_kernel<<<dim3(16, 8, 2), 256, ATTN_SMEM>>>(qlocs, klocs, vlens);

    gemm_o<<<dim3(32, 4), 256, GEMM1_SMEM>>>(bo, (float*)d_out);
}

// round 16
// speedup vs baseline: 2.7079x; 1.0254x over previous
#include <cuda_runtime.h>
#include <cuda_fp16.h>

#define Bb 2
#define Qq 2048
#define Kq 2048
#define DMm 512
#define Hh 8
#define Ff 5
#define DHh 64
#define LOG2E 1.4426950408889634f
#define M0OFF 12.0f   // fixed softmax offset (folded into bias table)

// bias table: d^2-indexed, LERP, float2 pairs (t_i, t_{i+1}); stores bias*LOG2E - M0OFF
#define TABF 512
#define TABC 2048
#define TABT (TABF + TABC)
#define U_COARSE_MAX 202.0f

// ---------------- scratch (__device__ globals; no allocation allowed) ----------------
__device__ __half g_sx[3][Bb*Qq*DMm];    // qs/ks/vs converted to fp16
__device__ __half g_wt[4][DMm*DMm];      // W transposed [n][k], fp16
__device__ __half g_qh[Bb*Qq*DMm];       // projected Q fp16
__device__ __half g_kh[Bb*Kq*DMm];       // projected K fp16
__device__ __half g_vt[Bb*Hh*DHh*Kq];    // projected V fp16, transposed [b][h][d][key]
__device__ __half g_ct[Bb*Qq*DMm];       // ctx fp16
__device__ float2 g_tab2[Hh*TABT];       // (bias*LOG2E - M0)[i], [i+1] pairs

// ---------------- helpers ----------------
__device__ __forceinline__ unsigned pack_h2(float a, float b){
    __half2 h = __floats2half2_rn(a, b);
    return *reinterpret_cast<unsigned*>(&h);
}
__device__ __forceinline__ void mma_f16(float c[4], const unsigned a[4], const unsigned b[2]){
    asm volatile(
        "mma.sync.aligned.m16n8k16.row.col.f32.f16.f16.f32 "
        "{%0,%1,%2,%3},{%4,%5,%6,%7},{%8,%9},{%0,%1,%2,%3};\n"
        : "+f"(c[0]), "+f"(c[1]), "+f"(c[2]), "+f"(c[3])
        : "r"(a[0]), "r"(a[1]), "r"(a[2]), "r"(a[3]), "r"(b[0]), "r"(b[1]));
}
__device__ __forceinline__ void ldsm4(unsigned r[4], const __half* p){
    unsigned a = (unsigned)__cvta_generic_to_shared(p);
    asm volatile("ldmatrix.sync.aligned.m8n8.x4.shared.b16 {%0,%1,%2,%3}, [%4];\n"
        : "=r"(r[0]), "=r"(r[1]), "=r"(r[2]), "=r"(r[3]) : "r"(a));
}
__device__ __forceinline__ float ex2f(float x){
    float y; asm("ex2.approx.f32 %0, %1;" : "=f"(y) : "f"(x)); return y;
}
__device__ __forceinline__ void cp16(void* sdst, const void* gsrc){
    unsigned s = (unsigned)__cvta_generic_to_shared(sdst);
    asm volatile("cp.async.cg.shared.global [%0], [%1], 16;\n" :: "r"(s), "l"(gsrc));
}
#define CP_COMMIT() asm volatile("cp.async.commit_group;\n" ::: "memory")
#define CP_WAIT0()  asm volatile("cp.async.wait_group 0;\n" ::: "memory")
#define CP_WAIT1()  asm volatile("cp.async.wait_group 1;\n" ::: "memory")

// ---------------- bias table ----------------
__device__ __forceinline__ float tisa_bias(int h, float d,
                                           const float* a, const float* b, const float* c){
    float s = 0.f;
    #pragma unroll
    for (int f = 0; f < Ff; f++){
        float af = a[h*Ff + f];
        float bf = fabsf(b[h*Ff + f]);
        float cf = c[h*Ff + f];
        float t  = d - cf;
        s += af * expf(-bf * t * t);
    }
    return s * LOG2E - M0OFF;   // fixed softmax offset folded in
}

__global__ void build_tab_kernel(const float* __restrict__ a,
                                 const float* __restrict__ b,
                                 const float* __restrict__ c){
    int h = blockIdx.x;
    for (int i = threadIdx.x; i < TABT; i += blockDim.x){
        float u0, u1;
        if (i < TABF){
            u0 = (float)i     * (1.0f/(TABF-1));
            u1 = (float)(i+1) * (1.0f/(TABF-1));
        } else {
            u0 = (float)(i - TABF)     * (U_COARSE_MAX/(TABC-1));
            u1 = (float)(i - TABF + 1) * (U_COARSE_MAX/(TABC-1));
        }
        float t0 = tisa_bias(h, sqrtf(u0), a, b, c);
        float t1 = tisa_bias(h, sqrtf(u1), a, b, c);
        g_tab2[h*TABT + i] = make_float2(t0, t1);
    }
}

// ---------------- prep: convert X inputs to fp16 ----------------
__global__ __launch_bounds__(256) void prep_cvt(const float* __restrict__ x0,
                                                const float* __restrict__ x1,
                                                const float* __restrict__ x2){
    int z = blockIdx.y;
    const float* X = (z == 0) ? x0 : (z == 1) ? x1 : x2;
    unsigned* dh = (unsigned*)&g_sx[z][0];
    const float4* src = (const float4*)X;
    #pragma unroll
    for (int t = 0; t < 2; t++){
        int i4 = blockIdx.x*512 + threadIdx.x + t*256;
        float4 v = src[i4];
        dh[i4*2]   = pack_h2(v.x, v.y);
        dh[i4*2+1] = pack_h2(v.z, v.w);
    }
}

// ---------------- prep: transpose + convert W -> g_wt[n][k] fp16 ----------------
__global__ __launch_bounds__(256) void prep_wt(const float* __restrict__ W0,
                                               const float* __restrict__ W1,
                                               const float* __restrict__ W2,
                                               const float* __restrict__ W3){
    __shared__ float S[64][65];
    int w = blockIdx.z;
    const float* W = (w==0)?W0:(w==1)?W1:(w==2)?W2:W3;
    int k0 = blockIdx.x*64, n0 = blockIdx.y*64, tid = threadIdx.x;
    #pragma unroll
    for (int t = 0; t < 4; t++){
        int i = tid + t*256;
        int row = i >> 4, c4 = i & 15;
        float4 v = *(const float4*)&W[(size_t)(k0+row)*512 + n0 + c4*4];
        S[row][c4*4+0] = v.x; S[row][c4*4+1] = v.y;
        S[row][c4*4+2] = v.z; S[row][c4*4+3] = v.w;
    }
    __syncthreads();
    #pragma unroll
    for (int t = 0; t < 8; t++){
        int i = tid + t*256;
        int n = i >> 5, kp = i & 31;
        unsigned p = pack_h2(S[kp*2][n], S[kp*2+1][n]);
        *(unsigned*)&g_wt[w][(size_t)(n0+n)*512 + k0 + kp*2] = p;
    }
}

// ---------------- single-A GEMM core: tile 128x128, k-chunk 64, 2-stage ----------------
#define G1STAGE 18432
#define GEMM1_SMEM (2*G1STAGE*2)

__device__ __forceinline__ void gemm1_issue(__half* st, int tid, int m0, int n0, int kc,
                                            const __half* Ah, const __half* Wt){
    __half* sX = st;
    __half* sW = st + 9216;
    const int kb = kc*64;
    #pragma unroll
    for (int t = 0; t < 4; t++){
        int i = tid + t*256;
        int row = i >> 3, j = i & 7;
        cp16(sX + row*72 + j*8, Ah + (size_t)(m0+row)*512 + kb + j*8);
        cp16(sW + row*72 + j*8, Wt + (size_t)(n0+row)*512 + kb + j*8);
    }
}

// mode 0: fp32 out; 1: fp16 -> g_qh; 2: fp16 -> g_kh; 3: fp16 transposed -> g_vt
__device__ __forceinline__ void gemm1_core(const __half* __restrict__ Ah,
                                           const __half* __restrict__ Wt,
                                           const float* __restrict__ bias,
                                           int mode, float* __restrict__ out_f,
                                           __half* gsm){
    const int tid  = threadIdx.x;
    const int lane = tid & 31;
    const int warp = tid >> 5;
    const int m0 = blockIdx.x * 128;
    const int n0 = blockIdx.y * 128;
    const int wm = (warp & 3) * 32;
    const int wn = (warp >> 2) * 64;
    const int lr  = lane & 7;
    const int lg1 = (lane >> 3) & 1;
    const int lg2 = (lane >> 4) & 1;

    float acc[2][8][4];
    #pragma unroll
    for (int mt = 0; mt < 2; mt++)
        #pragma unroll
        for (int nt = 0; nt < 8; nt++)
            #pragma unroll
            for (int j = 0; j < 4; j++) acc[mt][nt][j] = 0.f;

    gemm1_issue(gsm, tid, m0, n0, 0, Ah, Wt);
    CP_COMMIT();

    for (int kc = 0; kc < 8; kc++){
        if (kc + 1 < 8){
            gemm1_issue(gsm + ((kc+1)&1)*G1STAGE, tid, m0, n0, kc+1, Ah, Wt);
            CP_COMMIT();
            CP_WAIT1();
        } else {
            CP_WAIT0();
        }
        __syncthreads();

        __half* sX = gsm + (kc&1)*G1STAGE;
        __half* sW = sX + 9216;

        #pragma unroll
        for (int ks = 0; ks < 4; ks++){
            unsigned aH[2][4];
            #pragma unroll
            for (int mt = 0; mt < 2; mt++){
                int ao = (wm + mt*16 + lr + lg1*8)*72 + ks*16 + lg2*8;
                ldsm4(aH[mt], sX + ao);
            }
            unsigned bb[4][4];
            #pragma unroll
            for (int g = 0; g < 4; g++)
                ldsm4(bb[g], sW + (wn + g*16 + lr + lg2*8)*72 + ks*16 + lg1*8);
            #pragma unroll
            for (int nt = 0; nt < 8; nt++){
                const unsigned* bH = &bb[nt>>1][(nt&1)*2];
                #pragma unroll
                for (int mt = 0; mt < 2; mt++)
                    mma_f16(acc[mt][nt], aH[mt], bH);
            }
        }
        __syncthreads();
    }

    #pragma unroll
    for (int mt = 0; mt < 2; mt++)
        #pragma unroll
        for (int nt = 0; nt < 8; nt++){
            int r = m0 + wm + mt*16 + (lane>>2);
            int c = n0 + wn + nt*8 + (lane&3)*2;
            float b0 = bias[c], b1 = bias[c+1];
            float v00 = acc[mt][nt][0] + b0, v01 = acc[mt][nt][1] + b1;
            float v10 = acc[mt][nt][2] + b0, v11 = acc[mt][nt][3] + b1;
            if (mode == 0){
                *(float2*)&out_f[(size_t)r*512 + c]     = make_float2(v00, v01);
                *(float2*)&out_f[(size_t)(r+8)*512 + c] = make_float2(v10, v11);
            } else if (mode == 1){
                *(unsigned*)&g_qh[(size_t)r*512 + c]     = pack_h2(v00, v01);
                *(unsigned*)&g_qh[(size_t)(r+8)*512 + c] = pack_h2(v10, v11);
            } else if (mode == 2){
                *(unsigned*)&g_kh[(size_t)r*512 + c]     = pack_h2(v00, v01);
                *(unsigned*)&g_kh[(size_t)(r+8)*512 + c] = pack_h2(v10, v11);
            } else {
                int bidx = r >> 11;
                int key  = r & 2047;
                int d    = c & 63;
                int hh   = c >> 6;
                size_t vbase = ((size_t)(bidx*8 + hh))*64;
                g_vt[(vbase + d  )*2048 + key]     = __float2half_rn(v00);
                g_vt[(vbase + d+1)*2048 + key]     = __float2half_rn(v01);
                g_vt[(vbase + d  )*2048 + key + 8] = __float2half_rn(v10);
                g_vt[(vbase + d+1)*2048 + key + 8] = __float2half_rn(v11);
            }
        }
}

__global__ __launch_bounds__(256) void gemm_qkv(const float* bq, const float* bk, const float* bv){
    extern __shared__ __half gsm[];
    const int z = blockIdx.z;
    const float* bias = (z==0) ? bq : (z==1) ? bk : bv;
    gemm1_core(g_sx[z], g_wt[z], bias, z+1, nullptr, gsm);
}
__global__ __launch_bounds__(256) void gemm_o(const float* bo, float* out){
    extern __shared__ __half gsm[];
    gemm1_core(g_ct, g_wt[3], bo, 0, out, gsm);
}

// ---------------- fused flash attention (fixed-offset softmax, 3-stage, 1 barrier/chunk) ----
// smem: stab2 float2[TABT] (20KB) | klb[3][128]f | Qh [128*72] | Ks[3][64*72] | Vs[3][64*72]
#define ATTN_SMEM (TABT*8 + 3*128*4 + 128*72*2 + 6*(64*72*2))

__device__ __forceinline__ void attn_issue(__half* Ks, __half* Vs, float* klb,
                                           int tid, int b, int h, int k0,
                                           const float* __restrict__ klocs){
    #pragma unroll
    for (int t = 0; t < 2; t++){
        int i = tid + t*256;
        int row = i >> 3, j = i & 7;
        cp16(Ks + row*72 + j*8, g_kh + (size_t)(b*Kq + k0 + row)*512 + h*64 + j*8);
    }
    #pragma unroll
    for (int t = 0; t < 2; t++){
        int i = tid + t*256;
        int d = i >> 3, j = i & 7;
        cp16(Vs + d*72 + j*8, g_vt + ((size_t)(b*8 + h)*64 + d)*2048 + k0 + j*8);
    }
    if (tid < 32) cp16(klb + tid*4, klocs + (size_t)(b*Kq + k0)*2 + tid*4);
}

__global__ __launch_bounds__(256, 2) void attn_kernel(const float* __restrict__ qlocs,
                                                      const float* __restrict__ klocs,
                                                      const int* __restrict__ vlens){
    extern __shared__ char smem[];
    float2* stab2 = (float2*)smem;
    float*  klb   = (float*)(stab2 + TABT);           // [3][128]
    __half* Qh = (__half*)(klb + 384);
    __half* Ks = Qh + 128*72;                          // [3][64*72]
    __half* Vs = Ks + 3*64*72;                         // [3][64*72]

    const int tid  = threadIdx.x;
    const int lane = tid & 31;
    const int warp = tid >> 5;
    const int qt = blockIdx.x * 128;
    const int h  = blockIdx.y;
    const int b  = blockIdx.z;
    const int lr  = lane & 7;
    const int lg1 = (lane >> 3) & 1;
    const int lg2 = (lane >> 4) & 1;

    const int vl = vlens[b];
    const int nch = (vl + 63) >> 6;   // >= 16 since vl >= 1024

    // group 0: Q tile + chunk 0 ; group 1: chunk 1
    #pragma unroll
    for (int t = 0; t < 4; t++){
        int i = tid + t*256;
        int row = i >> 3, j = i & 7;
        cp16(Qh + row*72 + j*8, g_qh + (size_t)(b*Qq + qt + row)*512 + h*64 + j*8);
    }
    attn_issue(Ks, Vs, klb, tid, b, h, 0, klocs);
    CP_COMMIT();
    attn_issue(Ks + 64*72, Vs + 64*72, klb + 128, tid, b, h, 64, klocs);
    CP_COMMIT();

    // bias table while cp.async in flight (visible after first __syncthreads)
    for (int i = tid; i < TABT; i += 256) stab2[i] = g_tab2[h*TABT + i];

    const int r0 = warp*16 + (lane>>2);
    float qx0 = qlocs[((size_t)(b*Qq + qt + r0))*2 + 0];
    float qy0 = qlocs[((size_t)(b*Qq + qt + r0))*2 + 1];
    float qx1 = qlocs[((size_t)(b*Qq + qt + r0 + 8))*2 + 0];
    float qy1 = qlocs[((size_t)(b*Qq + qt + r0 + 8))*2 + 1];

    const float FSC = (float)(TABF-1);
    const float CSC = (float)(TABC-1)/U_COARSE_MAX;
    const float SC  = 0.125f * LOG2E;

    float l0 = 0.f, l1 = 0.f;
    float o[8][4];
    #pragma unroll
    for (int n = 0; n < 8; n++){ o[n][0]=0.f; o[n][1]=0.f; o[n][2]=0.f; o[n][3]=0.f; }

    int st = 0;        // stage of chunk kc
    for (int kc = 0; kc < nch; kc++){
        // wait for chunk kc's group (newest outstanding may be kc+1)
        if (kc + 1 < nch){ CP_WAIT1(); } else { CP_WAIT0(); }
        __syncthreads();   // publish chunk kc; also protects stage being refilled below

        // prefetch chunk kc+2 into stage (st+2)%3 (its readers finished at kc-1)
        if (kc + 2 < nch){
            int si = st + 2; if (si >= 3) si -= 3;
            attn_issue(Ks + si*64*72, Vs + si*64*72, klb + si*128, tid, b, h, (kc+2)*64, klocs);
            CP_COMMIT();
        }

        const __half* sK = Ks + st*64*72;
        const __half* sV = Vs + st*64*72;
        const float2* kl2 = (const float2*)(klb + st*128);
        const int k0 = kc * 64;

        float s[8][4];
        #pragma unroll
        for (int n = 0; n < 8; n++){ s[n][0]=0.f; s[n][1]=0.f; s[n][2]=0.f; s[n][3]=0.f; }

        #pragma unroll
        for (int ks = 0; ks < 4; ks++){
            unsigned aH[4];
            int ao = (warp*16 + lr + lg1*8)*72 + ks*16 + lg2*8;
            ldsm4(aH, Qh + ao);
            unsigned bk4[4][4];
            #pragma unroll
            for (int g = 0; g < 4; g++)
                ldsm4(bk4[g], sK + (g*16 + lr + lg2*8)*72 + ks*16 + lg1*8);
            #pragma unroll
            for (int n = 0; n < 8; n++){
                const unsigned* bH = &bk4[n>>1][(n&1)*2];
                mma_f16(s[n], aH, bH);
            }
        }

        // bias (fixed softmax offset folded in) + lerp table
        #pragma unroll
        for (int n = 0; n < 8; n++){
            #pragma unroll
            for (int j = 0; j < 2; j++){
                int kkl = n*8 + (lane&3)*2 + j;
                float2 kxy = kl2[kkl];

                float dx = qx0 - kxy.x, dy = qy0 - kxy.y;
                float u = fmaf(dx, dx, dy*dy);
                bool fine = (u < 1.0f);
                float fi = fine ? u*FSC : u*CSC;
                int ti = (int)fi;
                float w = fi - (float)ti;
                float2 tv = stab2[(fine ? 0 : TABF) + ti];
                s[n][j] = fmaf(s[n][j], SC, fmaf(w, tv.y - tv.x, tv.x));

                dx = qx1 - kxy.x; dy = qy1 - kxy.y;
                u = fmaf(dx, dx, dy*dy);
                fine = (u < 1.0f);
                fi = fine ? u*FSC : u*CSC;
                ti = (int)fi;
                w = fi - (float)ti;
                tv = stab2[(fine ? 0 : TABF) + ti];
                s[n][2+j] = fmaf(s[n][2+j], SC, fmaf(w, tv.y - tv.x, tv.x));
            }
        }

        // mask fix-up: only on the (at most one) partial chunk
        if (k0 + 64 > vl){
            #pragma unroll
            for (int n = 0; n < 8; n++){
                int kk0 = k0 + n*8 + (lane&3)*2;
                if (kk0     >= vl){ s[n][0] = -1e30f; s[n][2] = -1e30f; }
                if (kk0 + 1 >= vl){ s[n][1] = -1e30f; s[n][3] = -1e30f; }
            }
        }

        // P = 2^s; accumulate l
        #pragma unroll
        for (int n = 0; n < 8; n++){
            s[n][0] = ex2f(s[n][0]);
            s[n][1] = ex2f(s[n][1]);
            s[n][2] = ex2f(s[n][2]);
            s[n][3] = ex2f(s[n][3]);
            l0 += s[n][0] + s[n][1];
            l1 += s[n][2] + s[n][3];
        }

        // O += P V
        #pragma unroll
        for (int kk = 0; kk < 4; kk++){
            unsigned aH[4];
            aH[0] = pack_h2(s[2*kk][0],   s[2*kk][1]);
            aH[1] = pack_h2(s[2*kk][2],   s[2*kk][3]);
            aH[2] = pack_h2(s[2*kk+1][0], s[2*kk+1][1]);
            aH[3] = pack_h2(s[2*kk+1][2], s[2*kk+1][3]);
            unsigned bv4[4][4];
            #pragma unroll
            for (int g = 0; g < 4; g++)
                ldsm4(bv4[g], sV + (g*16 + lr + lg2*8)*72 + kk*16 + lg1*8);
            #pragma unroll
            for (int n = 0; n < 8; n++){
                const unsigned* bH = &bv4[n>>1][(n&1)*2];
                mma_f16(o[n], aH, bH);
            }
        }

        st++; if (st >= 3) st = 0;
    }

    l0 += __shfl_xor_sync(0xffffffffu, l0, 1);
    l0 += __shfl_xor_sync(0xffffffffu, l0, 2);
    l1 += __shfl_xor_sync(0xffffffffu, l1, 1);
    l1 += __shfl_xor_sync(0xffffffffu, l1, 2);
    float inv0 = 1.f / l0, inv1 = 1.f / l1;

    #pragma unroll
    for (int n = 0; n < 8; n++){
        int c = h*DHh + n*8 + (lane&3)*2;
        size_t r = (size_t)(b*Qq + qt + warp*16 + (lane>>2));
        *(unsigned*)&g_ct[r*512 + c]     = pack_h2(o[n][0]*inv0, o[n][1]*inv0);
        *(unsigned*)&g_ct[(r+8)*512 + c] = pack_h2(o[n][2]*inv1, o[n][3]*inv1);
    }
}

// ---------------- launch ----------------
extern "C" void kernel_launch(void* const* d_in, const int* in_sizes, int n_in,
                              void* d_out, int out_size){
    (void)in_sizes; (void)n_in; (void)out_size;
    const float* qs    = (const float*)d_in[0];
    const float* ks    = (const float*)d_in[1];
    const float* vs    = (const float*)d_in[2];
    const float* qlocs = (const float*)d_in[3];
    const float* klocs = (const float*)d_in[4];
    const float* Wq    = (const float*)d_in[5];
    const float* bq    = (const float*)d_in[6];
    const float* Wk    = (const float*)d_in[7];
    const float* bk    = (const float*)d_in[8];
    const float* Wv    = (const float*)d_in[9];
    const float* bv    = (const float*)d_in[10];
    const float* Wo    = (const float*)d_in[11];
    const float* bo    = (const float*)d_in[12];
    const float* pa    = (const float*)d_in[13];
    const float* pb    = (const float*)d_in[14];
    const float* pc    = (const float*)d_in[15];
    const int*   vlens = (const int*)d_in[16];

    cudaFuncSetAttribute(gemm_qkv,    cudaFuncAttributeMaxDynamicSharedMemorySize, GEMM1_SMEM);
    cudaFuncSetAttribute(gemm_o,      cudaFuncAttributeMaxDynamicSharedMemorySize, GEMM1_SMEM);
    cudaFuncSetAttribute(attn_kernel, cudaFuncAttributeMaxDynamicSharedMemorySize, ATTN_SMEM);

    build_tab_kernel<<<Hh, 256>>>(pa, pb, pc);
    prep_cvt<<<dim3(1024, 3), 256>>>(qs, ks, vs);
    prep_wt<<<dim3(8, 8, 4), 256>>>(Wq, Wk, Wv, Wo);

    gemm_qkv<<<dim3(32, 4, 3), 256, GEMM1_SMEM>>>(bq, bk, bv);

    attn_kernel<<<dim3(16, 8, 2), 256, ATTN_SMEM>>>(qlocs, klocs, vlens);

    gemm_o<<<dim3(32, 4), 256, GEMM1_SMEM>>>(bo, (float*)d_out);
}